// round 14
// baseline (speedup 1.0000x reference)
#include <cuda_runtime.h>
#include <cuda_fp16.h>
#include <math.h>
#include <stdint.h>

// Problem dims
#define BATCH  4
#define SEQ    2048
#define NH     16
#define HD     64
#define DMODEL 1024
#define MROWS  (BATCH*SEQ)   // 8192

// Scratch (device globals: allocation-free rule). fp16 storage.
__device__ __half g_xh[MROWS*DMODEL];      // x in fp16
__device__ __half g_wh[4*DMODEL*DMODEL];   // wq,wk,wv,wo in fp16
__device__ __half g_q[BATCH*NH*SEQ*HD];    // (b,h,s,d)
__device__ __half g_k[BATCH*NH*SEQ*HD];
__device__ __half g_v[BATCH*NH*SEQ*HD];
__device__ __half g_o[BATCH*SEQ*NH*HD];    // (b,s,h,d) == (8192, 1024)

// ===================== convert kernels ====================================
__global__ void cvt_x_kernel(const float* __restrict__ x)
{
    int idx = blockIdx.x*256 + threadIdx.x;
    float4 v = ((const float4*)x)[idx];
    uint2 o;
    ((__half2*)&o)[0] = __floats2half2_rn(v.x, v.y);
    ((__half2*)&o)[1] = __floats2half2_rn(v.z, v.w);
    ((uint2*)g_xh)[idx] = o;
}

__global__ void cvt_w_kernel(const float* __restrict__ wq, const float* __restrict__ wk,
                             const float* __restrict__ wv, const float* __restrict__ wo)
{
    const float* W = (blockIdx.y == 0) ? wq : (blockIdx.y == 1) ? wk
                    : (blockIdx.y == 2) ? wv : wo;
    __half* dst = g_wh + (size_t)blockIdx.y * DMODEL * DMODEL;
    int idx = blockIdx.x*256 + threadIdx.x;
    float4 v = ((const float4*)W)[idx];
    uint2 o;
    ((__half2*)&o)[0] = __floats2half2_rn(v.x, v.y);
    ((__half2*)&o)[1] = __floats2half2_rn(v.z, v.w);
    ((uint2*)dst)[idx] = o;
}

// ===================== asm helpers ========================================
#define CP16(dst, src) \
    asm volatile("cp.async.cg.shared.global [%0], [%1], 16;" :: "r"(dst), "l"(src))
#define CP_COMMIT() asm volatile("cp.async.commit_group;" ::: "memory")
#define CP_WAIT1()  asm volatile("cp.async.wait_group 1;" ::: "memory")
#define CP_WAIT0()  asm volatile("cp.async.wait_group 0;" ::: "memory")

#define LDM_X4(r0,r1,r2,r3,addr) \
    asm volatile("ldmatrix.sync.aligned.m8n8.x4.shared.b16 {%0,%1,%2,%3}, [%4];" \
        : "=r"(r0),"=r"(r1),"=r"(r2),"=r"(r3) : "r"(addr))
#define LDM_X4T(r0,r1,r2,r3,addr) \
    asm volatile("ldmatrix.sync.aligned.m8n8.x4.trans.shared.b16 {%0,%1,%2,%3}, [%4];" \
        : "=r"(r0),"=r"(r1),"=r"(r2),"=r"(r3) : "r"(addr))
#define LDM_X2T(r0,r1,addr) \
    asm volatile("ldmatrix.sync.aligned.m8n8.x2.trans.shared.b16 {%0,%1}, [%2];" \
        : "=r"(r0),"=r"(r1) : "r"(addr))
#define MMA16816(d,a,b) \
    asm volatile("mma.sync.aligned.m16n8k16.row.col.f32.f16.f16.f32 " \
        "{%0,%1,%2,%3}, {%4,%5,%6,%7}, {%8,%9}, {%0,%1,%2,%3};" \
        : "+f"((d)[0]),"+f"((d)[1]),"+f"((d)[2]),"+f"((d)[3]) \
        : "r"((a)[0]),"r"((a)[1]),"r"((a)[2]),"r"((a)[3]), "r"((b)[0]),"r"((b)[1]))

// ===================== raw-mma fp16 GEMM (R11 config, best) ===============
// Block 128x128, BK=64, 8 warps (4M x 2N), warp 32x64, 2 CTA/SM, 3-stage.
#define GBM 128
#define GBN 128
#define GBK 64
#define ASTB 144    // A row stride bytes (72 halfs)
#define BSTB 272    // B row stride bytes (136 halfs)
#define STAGE_BYTES (128*ASTB + 64*BSTB)     // 35840
#define GEMM_SMEM_BYTES (3*STAGE_BYTES)      // 107520
#define GOLD 136    // epilogue staging stride (halfs)

template<int MODE>
__device__ __forceinline__ void gemm_body(
    const __half* __restrict__ A, const __half* __restrict__ W,
    const float* __restrict__ bias, void* __restrict__ Cp)
{
    extern __shared__ char gsm[];
    const uint32_t sbase = (uint32_t)__cvta_generic_to_shared(gsm);

    const int tid  = threadIdx.x;
    const int lane = tid & 31;
    const int wid  = tid >> 5;
    const int wm   = wid >> 1;      // 0..3 -> M rows wm*32
    const int wn   = wid & 1;       // 0..1 -> N cols wn*64
    const int n0   = blockIdx.x * GBN;
    const int m0   = blockIdx.y * GBM;

    auto issue = [&](int kc, int st) {
        const uint32_t aOff = sbase + st*STAGE_BYTES;
        const uint32_t bOff = aOff + 128*ASTB;
        const int k0 = kc * GBK;
        #pragma unroll
        for (int it = 0; it < 4; it++) {
            int idx = tid + it*256;
            int r = idx >> 3, c8 = idx & 7;             // A: 128 x 8 chunks
            CP16(aOff + r*ASTB + c8*16,
                 (const char*)(A + (size_t)(m0 + r)*DMODEL + k0) + c8*16);
        }
        #pragma unroll
        for (int it = 0; it < 4; it++) {
            int idx = tid + it*256;
            int r = idx >> 4, c16 = idx & 15;           // B: 64 x 16 chunks
            CP16(bOff + r*BSTB + c16*16,
                 (const char*)(W + (size_t)(k0 + r)*DMODEL + n0) + c16*16);
        }
        CP_COMMIT();
    };

    float brg[8][2];
    {
        const float* bp = bias + n0 + wn*64 + (lane & 3)*2;
        #pragma unroll
        for (int n = 0; n < 8; n++) {
            float2 v = *(const float2*)(bp + n*8);
            brg[n][0] = v.x;  brg[n][1] = v.y;
        }
    }

    float acc[2][8][4];
    #pragma unroll
    for (int mf = 0; mf < 2; mf++)
        #pragma unroll
        for (int n = 0; n < 8; n++) {
            acc[mf][n][0] = brg[n][0];
            acc[mf][n][1] = brg[n][1];
            acc[mf][n][2] = brg[n][0];
            acc[mf][n][3] = brg[n][1];
        }

    issue(0, 0);
    issue(1, 1);

    const int NCH = DMODEL / GBK;   // 16
    for (int i = 0; i < NCH; i++) {
        const int st = i % 3;
        if (i < NCH - 1) { CP_WAIT1(); } else { CP_WAIT0(); }
        __syncthreads();
        if (i + 2 < NCH) issue(i + 2, (i + 2) % 3);

        const uint32_t aOff = sbase + st*STAGE_BYTES;
        const uint32_t bOff = aOff + 128*ASTB;

        #pragma unroll
        for (int kk = 0; kk < 4; kk++) {
            uint32_t a[2][4];
            #pragma unroll
            for (int mf = 0; mf < 2; mf++) {
                int row = wm*32 + mf*16 + (lane & 15);
                int col = kk*16 + (lane >> 4)*8;
                LDM_X4(a[mf][0], a[mf][1], a[mf][2], a[mf][3],
                       aOff + row*ASTB + col*2);
            }
            uint32_t b[8][2];
            #pragma unroll
            for (int p = 0; p < 4; p++) {
                int grp = lane >> 3, lx = lane & 7;
                int row = kk*16 + (grp & 1)*8 + lx;       // k index
                int col = wn*64 + p*16 + (grp >> 1)*8;    // n index
                LDM_X4T(b[2*p][0], b[2*p][1], b[2*p+1][0], b[2*p+1][1],
                        bOff + row*BSTB + col*2);
            }
            #pragma unroll
            for (int mf = 0; mf < 2; mf++)
                #pragma unroll
                for (int n = 0; n < 8; n++)
                    MMA16816(acc[mf][n], a[mf], b[n]);
        }
    }

    if (MODE == 1) {
        float* C = (float*)Cp;
        #pragma unroll
        for (int mf = 0; mf < 2; mf++) {
            int r0 = m0 + wm*32 + mf*16 + (lane >> 2);
            #pragma unroll
            for (int n = 0; n < 8; n++) {
                int c = n0 + wn*64 + n*8 + (lane & 3)*2;
                *(float2*)(C + (size_t)r0*DMODEL + c) =
                    make_float2(acc[mf][n][0], acc[mf][n][1]);
                *(float2*)(C + (size_t)(r0+8)*DMODEL + c) =
                    make_float2(acc[mf][n][2], acc[mf][n][3]);
            }
        }
    } else {
        __half* stg = (__half*)(gsm + 1*STAGE_BYTES);
        #pragma unroll
        for (int mf = 0; mf < 2; mf++) {
            int r = wm*32 + mf*16 + (lane >> 2);
            #pragma unroll
            for (int n = 0; n < 8; n++) {
                int c = wn*64 + n*8 + (lane & 3)*2;
                *(__half2*)&stg[r*GOLD + c] =
                    __floats2half2_rn(acc[mf][n][0], acc[mf][n][1]);
                *(__half2*)&stg[(r+8)*GOLD + c] =
                    __floats2half2_rn(acc[mf][n][2], acc[mf][n][3]);
            }
        }
        __syncthreads();
        __half* C = (__half*)Cp;
        #pragma unroll
        for (int it = 0; it < 8; it++) {
            int idx = tid + it*256;
            int r = idx >> 4, c8 = idx & 15;
            int row0 = m0 + r;
            int b = row0 >> 11;
            int s = row0 & (SEQ-1);
            int gcol = n0 + c8*8;
            int h  = gcol >> 6;
            int d0 = gcol & 63;
            uint4 v = *(const uint4*)&stg[r*GOLD + c8*8];
            *(uint4*)(C + (((size_t)(b*NH + h))*SEQ + s)*HD + d0) = v;
        }
    }
}

__global__ void __launch_bounds__(256, 2) gemm_qkv_kernel(
    const float* __restrict__ bq, const float* __restrict__ bk,
    const float* __restrict__ bv)
{
    const __half* W = g_wh + (size_t)blockIdx.z * DMODEL * DMODEL;
    const float* bb; __half* dst;
    if (blockIdx.z == 0)      { bb = bq; dst = g_q; }
    else if (blockIdx.z == 1) { bb = bk; dst = g_k; }
    else                      { bb = bv; dst = g_v; }
    gemm_body<0>(g_xh, W, bb, dst);
}

__global__ void __launch_bounds__(256, 2) gemm_out_kernel(
    const float* __restrict__ bo, float* __restrict__ out)
{
    gemm_body<1>(g_o, g_wh + (size_t)3*DMODEL*DMODEL, bo, out);
}

// ===================== Flash attention v7: 64-row Q tiles, 2 CTA/SM ========
// 256 threads, 8 warps (4M x 2kv); each warp: 16 M rows x 64-kv slice.
// Same per-warp structure as R8-best; two independent CTAs per SM decouple
// barrier/exp phases from MMA phases across CTAs.
#define ALD 72
#define ROWB 144
#define NT  (SEQ/128)
#define MQT 64                              // Q rows per CTA

#define Q_OFF   0                           // 64*144 = 9216
#define K0_OFF  9216
#define K1_OFF  (K0_OFF + 18432)            // 27648
#define V0_OFF  (K1_OFF + 18432)            // 46080
#define V1_OFF  (V0_OFF + 18432)            // 64512
#define ATT_SMEM_BYTES (V1_OFF + 18432)     // 82944 -> 2 CTA/SM

__device__ __forceinline__ uint32_t exp2_h2(float lo, float hi) {
    uint32_t h;
    asm("cvt.rn.f16x2.f32 %0, %1, %2;" : "=r"(h) : "f"(hi), "f"(lo));
    asm("ex2.approx.f16x2 %0, %0;" : "+r"(h));
    return h;
}

__global__ void __launch_bounds__(256, 2) attn_kernel()
{
    extern __shared__ char asmm[];
    const uint32_t sbase = (uint32_t)__cvta_generic_to_shared(asmm);

    const int tid  = threadIdx.x;
    const int lane = tid & 31;
    const int wid  = tid >> 5;
    const int wm   = wid >> 1;   // 0..3 (16 M rows each; M tile = 64)
    const int wn   = wid & 1;    // 0..1 (64-kv slice)
    const int bh   = blockIdx.y;
    const int q0   = blockIdx.x * MQT;

    const __half* Qg = g_q + (size_t)bh*SEQ*HD + (size_t)q0*HD;
    const __half* Kg = g_k + (size_t)bh*SEQ*HD;
    const __half* Vg = g_v + (size_t)bh*SEQ*HD;

    const uint32_t kOff[2] = { sbase + K0_OFF, sbase + K1_OFF };
    const uint32_t vOff[2] = { sbase + V0_OFF, sbase + V1_OFF };

    // ---- prologue: cp.async K0/V0 (1024 chunks each), Q (512), ones-pad ----
    #pragma unroll
    for (int it = 0; it < 4; it++) {
        int idx = tid + it*256;
        int r = idx >> 3, c8 = idx & 7;
        uint32_t so = (uint32_t)(r*ROWB + c8*16);
        CP16(kOff[0] + so, (const char*)Kg + idx*16);
        CP16(vOff[0] + so, (const char*)Vg + idx*16);
    }
    CP_COMMIT();

    {
        __half* Qs = (__half*)(asmm + Q_OFF);
        #pragma unroll
        for (int it = 0; it < 2; it++) {
            int idx = tid + it*256;
            int r = idx >> 3, c8 = idx & 7;
            *(uint4*)&Qs[r*ALD + c8*8] = ((const uint4*)Qg)[idx];
        }
        if (tid < 128) {   // ones-pad col 64 in both V buffers
            uint4 pad = make_uint4(0x00003C00u, 0u, 0u, 0u);
            *(uint4*)(asmm + V0_OFF + tid*ROWB + 128) = pad;
            *(uint4*)(asmm + V1_OFF + tid*ROWB + 128) = pad;
        }
    }
    CP_WAIT0();
    __syncthreads();

    // ---- persistent Q A-frags ----
    uint32_t qa[4][4];
    #pragma unroll
    for (int kc = 0; kc < 4; kc++) {
        int row = wm*16 + (lane & 15);
        int col = kc*16 + (lane >> 4)*8;
        uint32_t addr = sbase + Q_OFF + row*ROWB + col*2;
        LDM_X4(qa[kc][0], qa[kc][1], qa[kc][2], qa[kc][3], addr);
    }

    float oacc[9][4];
    #pragma unroll
    for (int n = 0; n < 9; n++)
        #pragma unroll
        for (int e = 0; e < 4; e++)
            oacc[n][e] = 0.f;

    const float EC = 0.36067376022224085f;   // 0.25 * log2(e)

    for (int kt = 0; kt < NT; kt++) {
        const int cur = kt & 1;

        if (kt + 1 < NT) {
            const __half* Kn = Kg + (size_t)(kt+1)*128*HD;
            const __half* Vn = Vg + (size_t)(kt+1)*128*HD;
            #pragma unroll
            for (int it = 0; it < 4; it++) {
                int idx = tid + it*256;
                int r = idx >> 3, c8 = idx & 7;
                uint32_t so = (uint32_t)(r*ROWB + c8*16);
                CP16(kOff[cur^1] + so, (const char*)Kn + idx*16);
                CP16(vOff[cur^1] + so, (const char*)Vn + idx*16);
            }
            CP_COMMIT();
        }

        float sacc[8][4];
        #pragma unroll
        for (int n = 0; n < 8; n++)
            #pragma unroll
            for (int e = 0; e < 4; e++)
                sacc[n][e] = 0.f;

        #pragma unroll
        for (int kc = 0; kc < 4; kc++) {
            uint32_t kb[8][2];
            #pragma unroll
            for (int p = 0; p < 4; p++) {
                int kv0 = wn*64 + p*16;
                int grp = lane >> 3, l = lane & 7;
                int row = kv0 + (grp >> 1)*8 + l;
                int col = kc*16 + (grp & 1)*8;
                uint32_t addr = kOff[cur] + row*ROWB + col*2;
                LDM_X4(kb[2*p][0], kb[2*p][1], kb[2*p+1][0], kb[2*p+1][1], addr);
            }
            #pragma unroll
            for (int n = 0; n < 8; n++)
                MMA16816(sacc[n], qa[kc], kb[n]);
        }

        #pragma unroll
        for (int l = 0; l < 4; l++) {
            uint32_t pa[4];
            {
                float* t0 = sacc[2*l];
                float* t1 = sacc[2*l+1];
                pa[0] = exp2_h2(t0[0]*EC, t0[1]*EC);
                pa[1] = exp2_h2(t0[2]*EC, t0[3]*EC);
                pa[2] = exp2_h2(t1[0]*EC, t1[1]*EC);
                pa[3] = exp2_h2(t1[2]*EC, t1[3]*EC);
            }
            uint32_t vb[9][2];
            #pragma unroll
            for (int p = 0; p < 4; p++) {
                int n0 = p*16;
                int grp = lane >> 3, lx = lane & 7;
                int row = (wn*64 + l*16) + (grp & 1)*8 + lx;
                int col = n0 + (grp >> 1)*8;
                uint32_t addr = vOff[cur] + row*ROWB + col*2;
                LDM_X4T(vb[2*p][0], vb[2*p][1], vb[2*p+1][0], vb[2*p+1][1], addr);
            }
            {
                int grp = (lane >> 3) & 1, lx = lane & 7;
                int row = (wn*64 + l*16) + grp*8 + lx;
                uint32_t addr = vOff[cur] + row*ROWB + 64*2;
                LDM_X2T(vb[8][0], vb[8][1], addr);
            }
            #pragma unroll
            for (int n = 0; n < 9; n++)
                MMA16816(oacc[n], pa, vb[n]);
        }

        if (kt + 1 < NT) CP_WAIT0();
        __syncthreads();
    }

    // ---- epilogue: reduce wn partials through smem, normalize, store ----
    float* Osum = (float*)asmm;   // 64 x 72 floats = 18432B (Q + start of K0)
    if (wn == 0) {
        int r = wm*16 + (lane >> 2);
        #pragma unroll
        for (int n = 0; n < 9; n++) {
            int c = n*8 + (lane & 3)*2;
            Osum[r*ALD + c]     = oacc[n][0];
            Osum[r*ALD + c + 1] = oacc[n][1];
            Osum[(r+8)*ALD + c]     = oacc[n][2];
            Osum[(r+8)*ALD + c + 1] = oacc[n][3];
        }
    }
    __syncthreads();
    if (wn == 1) {
        int r = wm*16 + (lane >> 2);
        #pragma unroll
        for (int n = 0; n < 9; n++) {
            int c = n*8 + (lane & 3)*2;
            Osum[r*ALD + c]     += oacc[n][0];
            Osum[r*ALD + c + 1] += oacc[n][1];
            Osum[(r+8)*ALD + c]     += oacc[n][2];
            Osum[(r+8)*ALD + c + 1] += oacc[n][3];
        }
    }
    __syncthreads();

    {
        int b = bh >> 4, h = bh & 15;
        int r       = tid >> 2;      // 64 rows, 4 threads/row
        int quarter = tid & 3;       // 16 cols each
        float inv = 1.0f / Osum[r*ALD + 64];
        const float* src = &Osum[r*ALD + quarter*16];
        __half* dst = g_o + (((size_t)(b*SEQ + q0 + r))*NH + h)*HD + quarter*16;
        #pragma unroll
        for (int c8 = 0; c8 < 2; c8++) {
            uint4 o;
            ((__half2*)&o)[0] = __floats2half2_rn(src[c8*8+0]*inv, src[c8*8+1]*inv);
            ((__half2*)&o)[1] = __floats2half2_rn(src[c8*8+2]*inv, src[c8*8+3]*inv);
            ((__half2*)&o)[2] = __floats2half2_rn(src[c8*8+4]*inv, src[c8*8+5]*inv);
            ((__half2*)&o)[3] = __floats2half2_rn(src[c8*8+6]*inv, src[c8*8+7]*inv);
            ((uint4*)dst)[c8] = o;
        }
    }
}

// ===================== launch =============================================
extern "C" void kernel_launch(void* const* d_in, const int* in_sizes, int n_in,
                              void* d_out, int out_size)
{
    const float* x  = (const float*)d_in[0];
    const float* wq = (const float*)d_in[1];
    const float* bq = (const float*)d_in[2];
    const float* wk = (const float*)d_in[3];
    const float* bk = (const float*)d_in[4];
    const float* wv = (const float*)d_in[5];
    const float* bv = (const float*)d_in[6];
    const float* wo = (const float*)d_in[7];
    const float* bo = (const float*)d_in[8];
    float* out = (float*)d_out;

    cudaFuncSetAttribute(gemm_qkv_kernel, cudaFuncAttributeMaxDynamicSharedMemorySize,
                         GEMM_SMEM_BYTES);
    cudaFuncSetAttribute(gemm_out_kernel, cudaFuncAttributeMaxDynamicSharedMemorySize,
                         GEMM_SMEM_BYTES);
    cudaFuncSetAttribute(attn_kernel, cudaFuncAttributeMaxDynamicSharedMemorySize,
                         ATT_SMEM_BYTES);

    cvt_x_kernel<<<MROWS*DMODEL/4/256, 256>>>(x);
    cvt_w_kernel<<<dim3(DMODEL*DMODEL/4/256, 4), 256>>>(wq, wk, wv, wo);
    gemm_qkv_kernel<<<dim3(DMODEL/GBN, MROWS/GBM, 3), 256, GEMM_SMEM_BYTES>>>(bq, bk, bv);
    attn_kernel<<<dim3(SEQ/MQT, BATCH*NH), 256, ATT_SMEM_BYTES>>>();
    gemm_out_kernel<<<dim3(DMODEL/GBN, MROWS/GBM), 256, GEMM_SMEM_BYTES>>>(bo, out);
}

// round 15
// speedup vs baseline: 1.0470x; 1.0470x over previous
#include <cuda_runtime.h>
#include <cuda_fp16.h>
#include <math.h>
#include <stdint.h>

// Problem dims
#define BATCH  4
#define SEQ    2048
#define NH     16
#define HD     64
#define DMODEL 1024
#define MROWS  (BATCH*SEQ)   // 8192

// Scratch (device globals: allocation-free rule). fp16 storage.
__device__ __half g_xh[MROWS*DMODEL];      // x in fp16
__device__ __half g_wh[4*DMODEL*DMODEL];   // wq,wk,wv,wo in fp16
__device__ __half g_q[BATCH*NH*SEQ*HD];    // (b,h,s,d)
__device__ __half g_k[BATCH*NH*SEQ*HD];
__device__ __half g_v[BATCH*NH*SEQ*HD];
__device__ __half g_o[BATCH*SEQ*NH*HD];    // (b,s,h,d) == (8192, 1024)

// ===================== merged convert kernel ===============================
// One launch converts x (2M float4) + 4 weights (1M float4 each) = 6M float4.
__global__ void cvt_all_kernel(const float* __restrict__ x,
                               const float* __restrict__ wq,
                               const float* __restrict__ wk,
                               const float* __restrict__ wv,
                               const float* __restrict__ wo)
{
    const int XQ = MROWS*DMODEL/4;          // 2M float4
    const int WQ = DMODEL*DMODEL/4;         // 256K float4 per weight
    int idx = blockIdx.x*256 + threadIdx.x; // total grid = XQ + 4*WQ
    const float* src;
    __half* dst;
    int off;
    if (idx < XQ) {
        src = x; dst = g_xh; off = idx;
    } else {
        int widx = idx - XQ;
        int w = widx / WQ;                  // 0..3
        off = widx - w*WQ;
        src = (w == 0) ? wq : (w == 1) ? wk : (w == 2) ? wv : wo;
        dst = g_wh + (size_t)w * DMODEL * DMODEL;
    }
    float4 v = ((const float4*)src)[off];
    uint2 o;
    ((__half2*)&o)[0] = __floats2half2_rn(v.x, v.y);
    ((__half2*)&o)[1] = __floats2half2_rn(v.z, v.w);
    ((uint2*)dst)[off] = o;
}

// ===================== asm helpers ========================================
#define CP16(dst, src) \
    asm volatile("cp.async.cg.shared.global [%0], [%1], 16;" :: "r"(dst), "l"(src))
#define CP_COMMIT() asm volatile("cp.async.commit_group;" ::: "memory")
#define CP_WAIT1()  asm volatile("cp.async.wait_group 1;" ::: "memory")
#define CP_WAIT0()  asm volatile("cp.async.wait_group 0;" ::: "memory")

#define LDM_X4(r0,r1,r2,r3,addr) \
    asm volatile("ldmatrix.sync.aligned.m8n8.x4.shared.b16 {%0,%1,%2,%3}, [%4];" \
        : "=r"(r0),"=r"(r1),"=r"(r2),"=r"(r3) : "r"(addr))
#define LDM_X4T(r0,r1,r2,r3,addr) \
    asm volatile("ldmatrix.sync.aligned.m8n8.x4.trans.shared.b16 {%0,%1,%2,%3}, [%4];" \
        : "=r"(r0),"=r"(r1),"=r"(r2),"=r"(r3) : "r"(addr))
#define LDM_X2T(r0,r1,addr) \
    asm volatile("ldmatrix.sync.aligned.m8n8.x2.trans.shared.b16 {%0,%1}, [%2];" \
        : "=r"(r0),"=r"(r1) : "r"(addr))
#define MMA16816(d,a,b) \
    asm volatile("mma.sync.aligned.m16n8k16.row.col.f32.f16.f16.f32 " \
        "{%0,%1,%2,%3}, {%4,%5,%6,%7}, {%8,%9}, {%0,%1,%2,%3};" \
        : "+f"((d)[0]),"+f"((d)[1]),"+f"((d)[2]),"+f"((d)[3]) \
        : "r"((a)[0]),"r"((a)[1]),"r"((a)[2]),"r"((a)[3]), "r"((b)[0]),"r"((b)[1]))

// ===================== raw-mma fp16 GEMM (R11 config, best) ===============
// Block 128x128, BK=64, 8 warps (4M x 2N), warp 32x64, 2 CTA/SM, 3-stage.
#define GBM 128
#define GBN 128
#define GBK 64
#define ASTB 144    // A row stride bytes (72 halfs)
#define BSTB 272    // B row stride bytes (136 halfs)
#define STAGE_BYTES (128*ASTB + 64*BSTB)     // 35840
#define GEMM_SMEM_BYTES (3*STAGE_BYTES)      // 107520
#define GOLD 136    // epilogue staging stride (halfs)

template<int MODE>
__device__ __forceinline__ void gemm_body(
    const __half* __restrict__ A, const __half* __restrict__ W,
    const float* __restrict__ bias, void* __restrict__ Cp)
{
    extern __shared__ char gsm[];
    const uint32_t sbase = (uint32_t)__cvta_generic_to_shared(gsm);

    const int tid  = threadIdx.x;
    const int lane = tid & 31;
    const int wid  = tid >> 5;
    const int wm   = wid >> 1;      // 0..3 -> M rows wm*32
    const int wn   = wid & 1;       // 0..1 -> N cols wn*64
    const int n0   = blockIdx.x * GBN;
    const int m0   = blockIdx.y * GBM;

    auto issue = [&](int kc, int st) {
        const uint32_t aOff = sbase + st*STAGE_BYTES;
        const uint32_t bOff = aOff + 128*ASTB;
        const int k0 = kc * GBK;
        #pragma unroll
        for (int it = 0; it < 4; it++) {
            int idx = tid + it*256;
            int r = idx >> 3, c8 = idx & 7;             // A: 128 x 8 chunks
            CP16(aOff + r*ASTB + c8*16,
                 (const char*)(A + (size_t)(m0 + r)*DMODEL + k0) + c8*16);
        }
        #pragma unroll
        for (int it = 0; it < 4; it++) {
            int idx = tid + it*256;
            int r = idx >> 4, c16 = idx & 15;           // B: 64 x 16 chunks
            CP16(bOff + r*BSTB + c16*16,
                 (const char*)(W + (size_t)(k0 + r)*DMODEL + n0) + c16*16);
        }
        CP_COMMIT();
    };

    float brg[8][2];
    {
        const float* bp = bias + n0 + wn*64 + (lane & 3)*2;
        #pragma unroll
        for (int n = 0; n < 8; n++) {
            float2 v = *(const float2*)(bp + n*8);
            brg[n][0] = v.x;  brg[n][1] = v.y;
        }
    }

    float acc[2][8][4];
    #pragma unroll
    for (int mf = 0; mf < 2; mf++)
        #pragma unroll
        for (int n = 0; n < 8; n++) {
            acc[mf][n][0] = brg[n][0];
            acc[mf][n][1] = brg[n][1];
            acc[mf][n][2] = brg[n][0];
            acc[mf][n][3] = brg[n][1];
        }

    issue(0, 0);
    issue(1, 1);

    const int NCH = DMODEL / GBK;   // 16
    for (int i = 0; i < NCH; i++) {
        const int st = i % 3;
        if (i < NCH - 1) { CP_WAIT1(); } else { CP_WAIT0(); }
        __syncthreads();
        if (i + 2 < NCH) issue(i + 2, (i + 2) % 3);

        const uint32_t aOff = sbase + st*STAGE_BYTES;
        const uint32_t bOff = aOff + 128*ASTB;

        #pragma unroll
        for (int kk = 0; kk < 4; kk++) {
            uint32_t a[2][4];
            #pragma unroll
            for (int mf = 0; mf < 2; mf++) {
                int row = wm*32 + mf*16 + (lane & 15);
                int col = kk*16 + (lane >> 4)*8;
                LDM_X4(a[mf][0], a[mf][1], a[mf][2], a[mf][3],
                       aOff + row*ASTB + col*2);
            }
            uint32_t b[8][2];
            #pragma unroll
            for (int p = 0; p < 4; p++) {
                int grp = lane >> 3, lx = lane & 7;
                int row = kk*16 + (grp & 1)*8 + lx;       // k index
                int col = wn*64 + p*16 + (grp >> 1)*8;    // n index
                LDM_X4T(b[2*p][0], b[2*p][1], b[2*p+1][0], b[2*p+1][1],
                        bOff + row*BSTB + col*2);
            }
            #pragma unroll
            for (int mf = 0; mf < 2; mf++)
                #pragma unroll
                for (int n = 0; n < 8; n++)
                    MMA16816(acc[mf][n], a[mf], b[n]);
        }
    }

    if (MODE == 1) {
        float* C = (float*)Cp;
        #pragma unroll
        for (int mf = 0; mf < 2; mf++) {
            int r0 = m0 + wm*32 + mf*16 + (lane >> 2);
            #pragma unroll
            for (int n = 0; n < 8; n++) {
                int c = n0 + wn*64 + n*8 + (lane & 3)*2;
                *(float2*)(C + (size_t)r0*DMODEL + c) =
                    make_float2(acc[mf][n][0], acc[mf][n][1]);
                *(float2*)(C + (size_t)(r0+8)*DMODEL + c) =
                    make_float2(acc[mf][n][2], acc[mf][n][3]);
            }
        }
    } else {
        // half staging (stage-1 buffer, 128 rows x GOLD=136 halfs = 34.8KB)
        __half* stg = (__half*)(gsm + 1*STAGE_BYTES);
        #pragma unroll
        for (int mf = 0; mf < 2; mf++) {
            int r = wm*32 + mf*16 + (lane >> 2);
            #pragma unroll
            for (int n = 0; n < 8; n++) {
                int c = wn*64 + n*8 + (lane & 3)*2;
                *(__half2*)&stg[r*GOLD + c] =
                    __floats2half2_rn(acc[mf][n][0], acc[mf][n][1]);
                *(__half2*)&stg[(r+8)*GOLD + c] =
                    __floats2half2_rn(acc[mf][n][2], acc[mf][n][3]);
            }
        }
        __syncthreads();
        __half* C = (__half*)Cp;
        #pragma unroll
        for (int it = 0; it < 8; it++) {
            int idx = tid + it*256;
            int r = idx >> 4, c8 = idx & 15;
            int row0 = m0 + r;
            int b = row0 >> 11;
            int s = row0 & (SEQ-1);
            int gcol = n0 + c8*8;
            int h  = gcol >> 6;
            int d0 = gcol & 63;
            uint4 v = *(const uint4*)&stg[r*GOLD + c8*8];
            *(uint4*)(C + (((size_t)(b*NH + h))*SEQ + s)*HD + d0) = v;
        }
    }
}

__global__ void __launch_bounds__(256, 2) gemm_qkv_kernel(
    const float* __restrict__ bq, const float* __restrict__ bk,
    const float* __restrict__ bv)
{
    const __half* W = g_wh + (size_t)blockIdx.z * DMODEL * DMODEL;
    const float* bb; __half* dst;
    if (blockIdx.z == 0)      { bb = bq; dst = g_q; }
    else if (blockIdx.z == 1) { bb = bk; dst = g_k; }
    else                      { bb = bv; dst = g_v; }
    gemm_body<0>(g_xh, W, bb, dst);
}

__global__ void __launch_bounds__(256, 2) gemm_out_kernel(
    const float* __restrict__ bo, float* __restrict__ out)
{
    gemm_body<1>(g_o, g_wh + (size_t)3*DMODEL*DMODEL, bo, out);
}

// ===================== Flash attention v4 (R8-best, verbatim) ==============
#define ALD 72
#define ROWB 144
#define NT  (SEQ/128)

#define Q_OFF   0
#define K0_OFF  18432
#define K1_OFF  36864
#define V0_OFF  55296
#define V1_OFF  73728
#define ATT_SMEM_BYTES 92160

__device__ __forceinline__ uint32_t exp2_h2(float lo, float hi) {
    uint32_t h;
    asm("cvt.rn.f16x2.f32 %0, %1, %2;" : "=r"(h) : "f"(hi), "f"(lo));
    asm("ex2.approx.f16x2 %0, %0;" : "+r"(h));
    return h;
}

__global__ void __launch_bounds__(512) attn_kernel()
{
    extern __shared__ char asmm[];
    const uint32_t sbase = (uint32_t)__cvta_generic_to_shared(asmm);

    const int tid  = threadIdx.x;
    const int lane = tid & 31;
    const int wid  = tid >> 5;
    const int wm   = wid >> 1;   // 0..7 (16 M rows each)
    const int wn   = wid & 1;    // 0..1 (64-kv slice)
    const int bh   = blockIdx.y;
    const int q0   = blockIdx.x * 128;

    const __half* Qg = g_q + (size_t)bh*SEQ*HD + (size_t)q0*HD;
    const __half* Kg = g_k + (size_t)bh*SEQ*HD;
    const __half* Vg = g_v + (size_t)bh*SEQ*HD;

    const uint32_t kOff[2] = { sbase + K0_OFF, sbase + K1_OFF };
    const uint32_t vOff[2] = { sbase + V0_OFF, sbase + V1_OFF };

    #pragma unroll
    for (int it = 0; it < 2; it++) {
        int idx = tid + it*512;
        int r = idx >> 3, c8 = idx & 7;
        uint32_t so = (uint32_t)(r*ROWB + c8*16);
        CP16(kOff[0] + so, (const char*)Kg + idx*16);
        CP16(vOff[0] + so, (const char*)Vg + idx*16);
    }
    CP_COMMIT();

    {
        __half* Qs = (__half*)(asmm + Q_OFF);
        #pragma unroll
        for (int it = 0; it < 2; it++) {
            int idx = tid + it*512;
            int r = idx >> 3, c8 = idx & 7;
            *(uint4*)&Qs[r*ALD + c8*8] = ((const uint4*)Qg)[idx];
        }
        if (tid < 128) {
            uint4 pad = make_uint4(0x00003C00u, 0u, 0u, 0u);  // {1h,0,...}
            *(uint4*)(asmm + V0_OFF + tid*ROWB + 128) = pad;
            *(uint4*)(asmm + V1_OFF + tid*ROWB + 128) = pad;
        }
    }
    CP_WAIT0();
    __syncthreads();

    uint32_t qa[4][4];
    #pragma unroll
    for (int kc = 0; kc < 4; kc++) {
        int row = wm*16 + (lane & 15);
        int col = kc*16 + (lane >> 4)*8;
        uint32_t addr = sbase + Q_OFF + row*ROWB + col*2;
        LDM_X4(qa[kc][0], qa[kc][1], qa[kc][2], qa[kc][3], addr);
    }

    float oacc[9][4];
    #pragma unroll
    for (int n = 0; n < 9; n++)
        #pragma unroll
        for (int e = 0; e < 4; e++)
            oacc[n][e] = 0.f;

    const float EC = 0.36067376022224085f;   // 0.25 * log2(e)

    for (int kt = 0; kt < NT; kt++) {
        const int cur = kt & 1;

        if (kt + 1 < NT) {
            const __half* Kn = Kg + (size_t)(kt+1)*128*HD;
            const __half* Vn = Vg + (size_t)(kt+1)*128*HD;
            #pragma unroll
            for (int it = 0; it < 2; it++) {
                int idx = tid + it*512;
                int r = idx >> 3, c8 = idx & 7;
                uint32_t so = (uint32_t)(r*ROWB + c8*16);
                CP16(kOff[cur^1] + so, (const char*)Kn + idx*16);
                CP16(vOff[cur^1] + so, (const char*)Vn + idx*16);
            }
            CP_COMMIT();
        }

        float sacc[8][4];
        #pragma unroll
        for (int n = 0; n < 8; n++)
            #pragma unroll
            for (int e = 0; e < 4; e++)
                sacc[n][e] = 0.f;

        #pragma unroll
        for (int kc = 0; kc < 4; kc++) {
            uint32_t kb[8][2];
            #pragma unroll
            for (int p = 0; p < 4; p++) {
                int kv0 = wn*64 + p*16;
                int grp = lane >> 3, l = lane & 7;
                int row = kv0 + (grp >> 1)*8 + l;
                int col = kc*16 + (grp & 1)*8;
                uint32_t addr = kOff[cur] + row*ROWB + col*2;
                LDM_X4(kb[2*p][0], kb[2*p][1], kb[2*p+1][0], kb[2*p+1][1], addr);
            }
            #pragma unroll
            for (int n = 0; n < 8; n++)
                MMA16816(sacc[n], qa[kc], kb[n]);
        }

        #pragma unroll
        for (int l = 0; l < 4; l++) {
            uint32_t pa[4];
            {
                float* t0 = sacc[2*l];
                float* t1 = sacc[2*l+1];
                pa[0] = exp2_h2(t0[0]*EC, t0[1]*EC);
                pa[1] = exp2_h2(t0[2]*EC, t0[3]*EC);
                pa[2] = exp2_h2(t1[0]*EC, t1[1]*EC);
                pa[3] = exp2_h2(t1[2]*EC, t1[3]*EC);
            }
            uint32_t vb[9][2];
            #pragma unroll
            for (int p = 0; p < 4; p++) {
                int n0 = p*16;
                int grp = lane >> 3, lx = lane & 7;
                int row = (wn*64 + l*16) + (grp & 1)*8 + lx;
                int col = n0 + (grp >> 1)*8;
                uint32_t addr = vOff[cur] + row*ROWB + col*2;
                LDM_X4T(vb[2*p][0], vb[2*p][1], vb[2*p+1][0], vb[2*p+1][1], addr);
            }
            {
                int grp = (lane >> 3) & 1, lx = lane & 7;
                int row = (wn*64 + l*16) + grp*8 + lx;
                uint32_t addr = vOff[cur] + row*ROWB + 64*2;
                LDM_X2T(vb[8][0], vb[8][1], addr);
            }
            #pragma unroll
            for (int n = 0; n < 9; n++)
                MMA16816(oacc[n], pa, vb[n]);
        }

        if (kt + 1 < NT) CP_WAIT0();
        __syncthreads();
    }

    float* Osum = (float*)(asmm + K0_OFF);
    if (wn == 0) {
        int r = wm*16 + (lane >> 2);
        #pragma unroll
        for (int n = 0; n < 9; n++) {
            int c = n*8 + (lane & 3)*2;
            Osum[r*ALD + c]     = oacc[n][0];
            Osum[r*ALD + c + 1] = oacc[n][1];
            Osum[(r+8)*ALD + c]     = oacc[n][2];
            Osum[(r+8)*ALD + c + 1] = oacc[n][3];
        }
    }
    __syncthreads();
    if (wn == 1) {
        int r = wm*16 + (lane >> 2);
        #pragma unroll
        for (int n = 0; n < 9; n++) {
            int c = n*8 + (lane & 3)*2;
            Osum[r*ALD + c]     += oacc[n][0];
            Osum[r*ALD + c + 1] += oacc[n][1];
            Osum[(r+8)*ALD + c]     += oacc[n][2];
            Osum[(r+8)*ALD + c + 1] += oacc[n][3];
        }
    }
    __syncthreads();

    {
        int b = bh >> 4, h = bh & 15;
        int r       = tid >> 2;
        int quarter = tid & 3;
        float inv = 1.0f / Osum[r*ALD + 64];
        const float* src = &Osum[r*ALD + quarter*16];
        __half* dst = g_o + (((size_t)(b*SEQ + q0 + r))*NH + h)*HD + quarter*16;
        #pragma unroll
        for (int c8 = 0; c8 < 2; c8++) {
            uint4 o;
            ((__half2*)&o)[0] = __floats2half2_rn(src[c8*8+0]*inv, src[c8*8+1]*inv);
            ((__half2*)&o)[1] = __floats2half2_rn(src[c8*8+2]*inv, src[c8*8+3]*inv);
            ((__half2*)&o)[2] = __floats2half2_rn(src[c8*8+4]*inv, src[c8*8+5]*inv);
            ((__half2*)&o)[3] = __floats2half2_rn(src[c8*8+6]*inv, src[c8*8+7]*inv);
            ((uint4*)dst)[c8] = o;
        }
    }
}

// ===================== launch =============================================
extern "C" void kernel_launch(void* const* d_in, const int* in_sizes, int n_in,
                              void* d_out, int out_size)
{
    const float* x  = (const float*)d_in[0];
    const float* wq = (const float*)d_in[1];
    const float* bq = (const float*)d_in[2];
    const float* wk = (const float*)d_in[3];
    const float* bk = (const float*)d_in[4];
    const float* wv = (const float*)d_in[5];
    const float* bv = (const float*)d_in[6];
    const float* wo = (const float*)d_in[7];
    const float* bo = (const float*)d_in[8];
    float* out = (float*)d_out;

    cudaFuncSetAttribute(gemm_qkv_kernel, cudaFuncAttributeMaxDynamicSharedMemorySize,
                         GEMM_SMEM_BYTES);
    cudaFuncSetAttribute(gemm_out_kernel, cudaFuncAttributeMaxDynamicSharedMemorySize,
                         GEMM_SMEM_BYTES);
    cudaFuncSetAttribute(attn_kernel, cudaFuncAttributeMaxDynamicSharedMemorySize,
                         ATT_SMEM_BYTES);

    const int CVT_BLOCKS = (MROWS*DMODEL/4 + 4*DMODEL*DMODEL/4) / 256;  // 24576
    cvt_all_kernel<<<CVT_BLOCKS, 256>>>(x, wq, wk, wv, wo);
    gemm_qkv_kernel<<<dim3(DMODEL/GBN, MROWS/GBM, 3), 256, GEMM_SMEM_BYTES>>>(bq, bk, bv);
    attn_kernel<<<dim3(SEQ/128, BATCH*NH), 512, ATT_SMEM_BYTES>>>();
    gemm_out_kernel<<<dim3(DMODEL/GBN, MROWS/GBM), 256, GEMM_SMEM_BYTES>>>(bo, out);
}

// round 16
// speedup vs baseline: 1.0639x; 1.0161x over previous
#include <cuda_runtime.h>
#include <cuda_fp16.h>
#include <math.h>
#include <stdint.h>

// Problem dims
#define BATCH  4
#define SEQ    2048
#define NH     16
#define HD     64
#define DMODEL 1024
#define MROWS  (BATCH*SEQ)   // 8192

// Scratch (device globals: allocation-free rule). fp16 storage.
__device__ __half g_xh[MROWS*DMODEL];      // x in fp16
__device__ __half g_wh[4*DMODEL*DMODEL];   // wq,wk,wv,wo in fp16
__device__ __half g_q[BATCH*NH*SEQ*HD];    // (b,h,s,d)
__device__ __half g_k[BATCH*NH*SEQ*HD];
__device__ __half g_v[BATCH*NH*SEQ*HD];
__device__ __half g_o[BATCH*SEQ*NH*HD];    // (b,s,h,d) == (8192, 1024)

// ===================== merged convert kernel ===============================
__global__ void cvt_all_kernel(const float* __restrict__ x,
                               const float* __restrict__ wq,
                               const float* __restrict__ wk,
                               const float* __restrict__ wv,
                               const float* __restrict__ wo)
{
    const int XQ = MROWS*DMODEL/4;          // 2M float4
    const int WQ = DMODEL*DMODEL/4;         // 256K float4 per weight
    int idx = blockIdx.x*256 + threadIdx.x;
    const float* src;
    __half* dst;
    int off;
    if (idx < XQ) {
        src = x; dst = g_xh; off = idx;
    } else {
        int widx = idx - XQ;
        int w = widx / WQ;                  // 0..3
        off = widx - w*WQ;
        src = (w == 0) ? wq : (w == 1) ? wk : (w == 2) ? wv : wo;
        dst = g_wh + (size_t)w * DMODEL * DMODEL;
    }
    float4 v = ((const float4*)src)[off];
    uint2 o;
    ((__half2*)&o)[0] = __floats2half2_rn(v.x, v.y);
    ((__half2*)&o)[1] = __floats2half2_rn(v.z, v.w);
    ((uint2*)dst)[off] = o;
}

// ===================== asm helpers ========================================
#define CP16(dst, src) \
    asm volatile("cp.async.cg.shared.global [%0], [%1], 16;" :: "r"(dst), "l"(src))
#define CP_COMMIT() asm volatile("cp.async.commit_group;" ::: "memory")
#define CP_WAIT1()  asm volatile("cp.async.wait_group 1;" ::: "memory")
#define CP_WAIT0()  asm volatile("cp.async.wait_group 0;" ::: "memory")

#define LDM_X4(r0,r1,r2,r3,addr) \
    asm volatile("ldmatrix.sync.aligned.m8n8.x4.shared.b16 {%0,%1,%2,%3}, [%4];" \
        : "=r"(r0),"=r"(r1),"=r"(r2),"=r"(r3) : "r"(addr))
#define LDM_X4T(r0,r1,r2,r3,addr) \
    asm volatile("ldmatrix.sync.aligned.m8n8.x4.trans.shared.b16 {%0,%1,%2,%3}, [%4];" \
        : "=r"(r0),"=r"(r1),"=r"(r2),"=r"(r3) : "r"(addr))
#define LDM_X2T(r0,r1,addr) \
    asm volatile("ldmatrix.sync.aligned.m8n8.x2.trans.shared.b16 {%0,%1}, [%2];" \
        : "=r"(r0),"=r"(r1) : "r"(addr))
#define MMA16816(d,a,b) \
    asm volatile("mma.sync.aligned.m16n8k16.row.col.f32.f16.f16.f32 " \
        "{%0,%1,%2,%3}, {%4,%5,%6,%7}, {%8,%9}, {%0,%1,%2,%3};" \
        : "+f"((d)[0]),"+f"((d)[1]),"+f"((d)[2]),"+f"((d)[3]) \
        : "r"((a)[0]),"r"((a)[1]),"r"((a)[2]),"r"((a)[3]), "r"((b)[0]),"r"((b)[1]))

// ===================== raw-mma fp16 GEMM (R11 config, best) ===============
// Block 128x128, BK=64, 8 warps (4M x 2N), warp 32x64, 2 CTA/SM, 3-stage.
#define GBM 128
#define GBN 128
#define GBK 64
#define ASTB 144    // A row stride bytes (72 halfs)
#define BSTB 272    // B row stride bytes (136 halfs)
#define STAGE_BYTES (128*ASTB + 64*BSTB)     // 35840
#define GEMM_SMEM_BYTES (3*STAGE_BYTES)      // 107520
#define GOLD 136    // epilogue staging stride (halfs)

template<int MODE>
__device__ __forceinline__ void gemm_body(
    const __half* __restrict__ A, const __half* __restrict__ W,
    const float* __restrict__ bias, void* __restrict__ Cp)
{
    extern __shared__ char gsm[];
    const uint32_t sbase = (uint32_t)__cvta_generic_to_shared(gsm);

    const int tid  = threadIdx.x;
    const int lane = tid & 31;
    const int wid  = tid >> 5;
    const int wm   = wid >> 1;      // 0..3 -> M rows wm*32
    const int wn   = wid & 1;       // 0..1 -> N cols wn*64
    const int n0   = blockIdx.x * GBN;
    const int m0   = blockIdx.y * GBM;

    auto issue = [&](int kc, int st) {
        const uint32_t aOff = sbase + st*STAGE_BYTES;
        const uint32_t bOff = aOff + 128*ASTB;
        const int k0 = kc * GBK;
        #pragma unroll
        for (int it = 0; it < 4; it++) {
            int idx = tid + it*256;
            int r = idx >> 3, c8 = idx & 7;             // A: 128 x 8 chunks
            CP16(aOff + r*ASTB + c8*16,
                 (const char*)(A + (size_t)(m0 + r)*DMODEL + k0) + c8*16);
        }
        #pragma unroll
        for (int it = 0; it < 4; it++) {
            int idx = tid + it*256;
            int r = idx >> 4, c16 = idx & 15;           // B: 64 x 16 chunks
            CP16(bOff + r*BSTB + c16*16,
                 (const char*)(W + (size_t)(k0 + r)*DMODEL + n0) + c16*16);
        }
        CP_COMMIT();
    };

    float brg[8][2];
    {
        const float* bp = bias + n0 + wn*64 + (lane & 3)*2;
        #pragma unroll
        for (int n = 0; n < 8; n++) {
            float2 v = *(const float2*)(bp + n*8);
            brg[n][0] = v.x;  brg[n][1] = v.y;
        }
    }

    float acc[2][8][4];
    #pragma unroll
    for (int mf = 0; mf < 2; mf++)
        #pragma unroll
        for (int n = 0; n < 8; n++) {
            acc[mf][n][0] = brg[n][0];
            acc[mf][n][1] = brg[n][1];
            acc[mf][n][2] = brg[n][0];
            acc[mf][n][3] = brg[n][1];
        }

    issue(0, 0);
    issue(1, 1);

    const int NCH = DMODEL / GBK;   // 16
    for (int i = 0; i < NCH; i++) {
        const int st = i % 3;
        if (i < NCH - 1) { CP_WAIT1(); } else { CP_WAIT0(); }
        __syncthreads();
        if (i + 2 < NCH) issue(i + 2, (i + 2) % 3);

        const uint32_t aOff = sbase + st*STAGE_BYTES;
        const uint32_t bOff = aOff + 128*ASTB;

        #pragma unroll
        for (int kk = 0; kk < 4; kk++) {
            uint32_t a[2][4];
            #pragma unroll
            for (int mf = 0; mf < 2; mf++) {
                int row = wm*32 + mf*16 + (lane & 15);
                int col = kk*16 + (lane >> 4)*8;
                LDM_X4(a[mf][0], a[mf][1], a[mf][2], a[mf][3],
                       aOff + row*ASTB + col*2);
            }
            uint32_t b[8][2];
            #pragma unroll
            for (int p = 0; p < 4; p++) {
                int grp = lane >> 3, lx = lane & 7;
                int row = kk*16 + (grp & 1)*8 + lx;       // k index
                int col = wn*64 + p*16 + (grp >> 1)*8;    // n index
                LDM_X4T(b[2*p][0], b[2*p][1], b[2*p+1][0], b[2*p+1][1],
                        bOff + row*BSTB + col*2);
            }
            #pragma unroll
            for (int mf = 0; mf < 2; mf++)
                #pragma unroll
                for (int n = 0; n < 8; n++)
                    MMA16816(acc[mf][n], a[mf], b[n]);
        }
    }

    if (MODE == 1) {
        float* C = (float*)Cp;
        #pragma unroll
        for (int mf = 0; mf < 2; mf++) {
            int r0 = m0 + wm*32 + mf*16 + (lane >> 2);
            #pragma unroll
            for (int n = 0; n < 8; n++) {
                int c = n0 + wn*64 + n*8 + (lane & 3)*2;
                *(float2*)(C + (size_t)r0*DMODEL + c) =
                    make_float2(acc[mf][n][0], acc[mf][n][1]);
                *(float2*)(C + (size_t)(r0+8)*DMODEL + c) =
                    make_float2(acc[mf][n][2], acc[mf][n][3]);
            }
        }
    } else {
        // half staging (stage-1 buffer, 128 rows x GOLD=136 halfs = 34.8KB)
        __half* stg = (__half*)(gsm + 1*STAGE_BYTES);
        #pragma unroll
        for (int mf = 0; mf < 2; mf++) {
            int r = wm*32 + mf*16 + (lane >> 2);
            #pragma unroll
            for (int n = 0; n < 8; n++) {
                int c = wn*64 + n*8 + (lane & 3)*2;
                *(__half2*)&stg[r*GOLD + c] =
                    __floats2half2_rn(acc[mf][n][0], acc[mf][n][1]);
                *(__half2*)&stg[(r+8)*GOLD + c] =
                    __floats2half2_rn(acc[mf][n][2], acc[mf][n][3]);
            }
        }
        __syncthreads();
        __half* C = (__half*)Cp;
        #pragma unroll
        for (int it = 0; it < 8; it++) {
            int idx = tid + it*256;
            int r = idx >> 4, c8 = idx & 15;
            int row0 = m0 + r;
            int b = row0 >> 11;
            int s = row0 & (SEQ-1);
            int gcol = n0 + c8*8;
            int h  = gcol >> 6;
            int d0 = gcol & 63;
            uint4 v = *(const uint4*)&stg[r*GOLD + c8*8];
            *(uint4*)(C + (((size_t)(b*NH + h))*SEQ + s)*HD + d0) = v;
        }
    }
}

__global__ void __launch_bounds__(256, 2) gemm_qkv_kernel(
    const float* __restrict__ bq, const float* __restrict__ bk,
    const float* __restrict__ bv)
{
    const __half* W = g_wh + (size_t)blockIdx.z * DMODEL * DMODEL;
    const float* bb; __half* dst;
    if (blockIdx.z == 0)      { bb = bq; dst = g_q; }
    else if (blockIdx.z == 1) { bb = bk; dst = g_k; }
    else                      { bb = bv; dst = g_v; }
    gemm_body<0>(g_xh, W, bb, dst);
}

__global__ void __launch_bounds__(256, 2) gemm_out_kernel(
    const float* __restrict__ bo, float* __restrict__ out)
{
    gemm_body<1>(g_o, g_wh + (size_t)3*DMODEL*DMODEL, bo, out);
}

// ===================== Flash attention v8: R8-best + peeled l=3 PV =========
// 512 threads, 16 warps (8M x 2kv). The l=3 chunk's exp+LDSM happen before
// the per-iter WAIT+barrier; its 9 MMAs issue after (register-only), so the
// tensor-pipe drain overlaps the next iteration's cp.async + S-phase LDSM.
#define ALD 72
#define ROWB 144
#define NT  (SEQ/128)

#define Q_OFF   0
#define K0_OFF  18432
#define K1_OFF  36864
#define V0_OFF  55296
#define V1_OFF  73728
#define ATT_SMEM_BYTES 92160

__device__ __forceinline__ uint32_t exp2_h2(float lo, float hi) {
    uint32_t h;
    asm("cvt.rn.f16x2.f32 %0, %1, %2;" : "=r"(h) : "f"(hi), "f"(lo));
    asm("ex2.approx.f16x2 %0, %0;" : "+r"(h));
    return h;
}

__global__ void __launch_bounds__(512) attn_kernel()
{
    extern __shared__ char asmm[];
    const uint32_t sbase = (uint32_t)__cvta_generic_to_shared(asmm);

    const int tid  = threadIdx.x;
    const int lane = tid & 31;
    const int wid  = tid >> 5;
    const int wm   = wid >> 1;   // 0..7 (16 M rows each)
    const int wn   = wid & 1;    // 0..1 (64-kv slice)
    const int bh   = blockIdx.y;
    const int q0   = blockIdx.x * 128;

    const __half* Qg = g_q + (size_t)bh*SEQ*HD + (size_t)q0*HD;
    const __half* Kg = g_k + (size_t)bh*SEQ*HD;
    const __half* Vg = g_v + (size_t)bh*SEQ*HD;

    const uint32_t kOff[2] = { sbase + K0_OFF, sbase + K1_OFF };
    const uint32_t vOff[2] = { sbase + V0_OFF, sbase + V1_OFF };

    #pragma unroll
    for (int it = 0; it < 2; it++) {
        int idx = tid + it*512;
        int r = idx >> 3, c8 = idx & 7;
        uint32_t so = (uint32_t)(r*ROWB + c8*16);
        CP16(kOff[0] + so, (const char*)Kg + idx*16);
        CP16(vOff[0] + so, (const char*)Vg + idx*16);
    }
    CP_COMMIT();

    {
        __half* Qs = (__half*)(asmm + Q_OFF);
        #pragma unroll
        for (int it = 0; it < 2; it++) {
            int idx = tid + it*512;
            int r = idx >> 3, c8 = idx & 7;
            *(uint4*)&Qs[r*ALD + c8*8] = ((const uint4*)Qg)[idx];
        }
        if (tid < 128) {
            uint4 pad = make_uint4(0x00003C00u, 0u, 0u, 0u);  // {1h,0,...}
            *(uint4*)(asmm + V0_OFF + tid*ROWB + 128) = pad;
            *(uint4*)(asmm + V1_OFF + tid*ROWB + 128) = pad;
        }
    }
    CP_WAIT0();
    __syncthreads();

    uint32_t qa[4][4];
    #pragma unroll
    for (int kc = 0; kc < 4; kc++) {
        int row = wm*16 + (lane & 15);
        int col = kc*16 + (lane >> 4)*8;
        uint32_t addr = sbase + Q_OFF + row*ROWB + col*2;
        LDM_X4(qa[kc][0], qa[kc][1], qa[kc][2], qa[kc][3], addr);
    }

    float oacc[9][4];
    #pragma unroll
    for (int n = 0; n < 9; n++)
        #pragma unroll
        for (int e = 0; e < 4; e++)
            oacc[n][e] = 0.f;

    const float EC = 0.36067376022224085f;   // 0.25 * log2(e)

    for (int kt = 0; kt < NT; kt++) {
        const int cur = kt & 1;

        if (kt + 1 < NT) {
            const __half* Kn = Kg + (size_t)(kt+1)*128*HD;
            const __half* Vn = Vg + (size_t)(kt+1)*128*HD;
            #pragma unroll
            for (int it = 0; it < 2; it++) {
                int idx = tid + it*512;
                int r = idx >> 3, c8 = idx & 7;
                uint32_t so = (uint32_t)(r*ROWB + c8*16);
                CP16(kOff[cur^1] + so, (const char*)Kn + idx*16);
                CP16(vOff[cur^1] + so, (const char*)Vn + idx*16);
            }
            CP_COMMIT();
        }

        float sacc[8][4];
        #pragma unroll
        for (int n = 0; n < 8; n++)
            #pragma unroll
            for (int e = 0; e < 4; e++)
                sacc[n][e] = 0.f;

        #pragma unroll
        for (int kc = 0; kc < 4; kc++) {
            uint32_t kb[8][2];
            #pragma unroll
            for (int p = 0; p < 4; p++) {
                int kv0 = wn*64 + p*16;
                int grp = lane >> 3, l = lane & 7;
                int row = kv0 + (grp >> 1)*8 + l;
                int col = kc*16 + (grp & 1)*8;
                uint32_t addr = kOff[cur] + row*ROWB + col*2;
                LDM_X4(kb[2*p][0], kb[2*p][1], kb[2*p+1][0], kb[2*p+1][1], addr);
            }
            #pragma unroll
            for (int n = 0; n < 8; n++)
                MMA16816(sacc[n], qa[kc], kb[n]);
        }

        // ---- PV chunks l=0..2: exp + LDSM + MMA (normal path) ----
        #pragma unroll
        for (int l = 0; l < 3; l++) {
            uint32_t pa[4];
            {
                float* t0 = sacc[2*l];
                float* t1 = sacc[2*l+1];
                pa[0] = exp2_h2(t0[0]*EC, t0[1]*EC);
                pa[1] = exp2_h2(t0[2]*EC, t0[3]*EC);
                pa[2] = exp2_h2(t1[0]*EC, t1[1]*EC);
                pa[3] = exp2_h2(t1[2]*EC, t1[3]*EC);
            }
            uint32_t vb[9][2];
            #pragma unroll
            for (int p = 0; p < 4; p++) {
                int n0 = p*16;
                int grp = lane >> 3, lx = lane & 7;
                int row = (wn*64 + l*16) + (grp & 1)*8 + lx;
                int col = n0 + (grp >> 1)*8;
                uint32_t addr = vOff[cur] + row*ROWB + col*2;
                LDM_X4T(vb[2*p][0], vb[2*p][1], vb[2*p+1][0], vb[2*p+1][1], addr);
            }
            {
                int grp = (lane >> 3) & 1, lx = lane & 7;
                int row = (wn*64 + l*16) + grp*8 + lx;
                uint32_t addr = vOff[cur] + row*ROWB + 64*2;
                LDM_X2T(vb[8][0], vb[8][1], addr);
            }
            #pragma unroll
            for (int n = 0; n < 9; n++)
                MMA16816(oacc[n], pa, vb[n]);
        }

        // ---- PV chunk l=3: exp + LDSM BEFORE the barrier; MMAs AFTER ----
        uint32_t pa3[4];
        {
            float* t0 = sacc[6];
            float* t1 = sacc[7];
            pa3[0] = exp2_h2(t0[0]*EC, t0[1]*EC);
            pa3[1] = exp2_h2(t0[2]*EC, t0[3]*EC);
            pa3[2] = exp2_h2(t1[0]*EC, t1[1]*EC);
            pa3[3] = exp2_h2(t1[2]*EC, t1[3]*EC);
        }
        uint32_t vb3[9][2];
        #pragma unroll
        for (int p = 0; p < 4; p++) {
            int n0 = p*16;
            int grp = lane >> 3, lx = lane & 7;
            int row = (wn*64 + 48) + (grp & 1)*8 + lx;
            int col = n0 + (grp >> 1)*8;
            uint32_t addr = vOff[cur] + row*ROWB + col*2;
            LDM_X4T(vb3[2*p][0], vb3[2*p][1], vb3[2*p+1][0], vb3[2*p+1][1], addr);
        }
        {
            int grp = (lane >> 3) & 1, lx = lane & 7;
            int row = (wn*64 + 48) + grp*8 + lx;
            uint32_t addr = vOff[cur] + row*ROWB + 64*2;
            LDM_X2T(vb3[8][0], vb3[8][1], addr);
        }

        if (kt + 1 < NT) {
            CP_WAIT0();
            __syncthreads();
        }

        // register-only MMAs overlap next iteration's loads past the barrier
        #pragma unroll
        for (int n = 0; n < 9; n++)
            MMA16816(oacc[n], pa3, vb3[n]);
    }
    __syncthreads();   // all smem reads done before epilogue overwrite

    float* Osum = (float*)(asmm + K0_OFF);
    if (wn == 0) {
        int r = wm*16 + (lane >> 2);
        #pragma unroll
        for (int n = 0; n < 9; n++) {
            int c = n*8 + (lane & 3)*2;
            Osum[r*ALD + c]     = oacc[n][0];
            Osum[r*ALD + c + 1] = oacc[n][1];
            Osum[(r+8)*ALD + c]     = oacc[n][2];
            Osum[(r+8)*ALD + c + 1] = oacc[n][3];
        }
    }
    __syncthreads();
    if (wn == 1) {
        int r = wm*16 + (lane >> 2);
        #pragma unroll
        for (int n = 0; n < 9; n++) {
            int c = n*8 + (lane & 3)*2;
            Osum[r*ALD + c]     += oacc[n][0];
            Osum[r*ALD + c + 1] += oacc[n][1];
            Osum[(r+8)*ALD + c]     += oacc[n][2];
            Osum[(r+8)*ALD + c + 1] += oacc[n][3];
        }
    }
    __syncthreads();

    {
        int b = bh >> 4, h = bh & 15;
        int r       = tid >> 2;
        int quarter = tid & 3;
        float inv = 1.0f / Osum[r*ALD + 64];
        const float* src = &Osum[r*ALD + quarter*16];
        __half* dst = g_o + (((size_t)(b*SEQ + q0 + r))*NH + h)*HD + quarter*16;
        #pragma unroll
        for (int c8 = 0; c8 < 2; c8++) {
            uint4 o;
            ((__half2*)&o)[0] = __floats2half2_rn(src[c8*8+0]*inv, src[c8*8+1]*inv);
            ((__half2*)&o)[1] = __floats2half2_rn(src[c8*8+2]*inv, src[c8*8+3]*inv);
            ((__half2*)&o)[2] = __floats2half2_rn(src[c8*8+4]*inv, src[c8*8+5]*inv);
            ((__half2*)&o)[3] = __floats2half2_rn(src[c8*8+6]*inv, src[c8*8+7]*inv);
            ((uint4*)dst)[c8] = o;
        }
    }
}

// ===================== launch =============================================
extern "C" void kernel_launch(void* const* d_in, const int* in_sizes, int n_in,
                              void* d_out, int out_size)
{
    const float* x  = (const float*)d_in[0];
    const float* wq = (const float*)d_in[1];
    const float* bq = (const float*)d_in[2];
    const float* wk = (const float*)d_in[3];
    const float* bk = (const float*)d_in[4];
    const float* wv = (const float*)d_in[5];
    const float* bv = (const float*)d_in[6];
    const float* wo = (const float*)d_in[7];
    const float* bo = (const float*)d_in[8];
    float* out = (float*)d_out;

    cudaFuncSetAttribute(gemm_qkv_kernel, cudaFuncAttributeMaxDynamicSharedMemorySize,
                         GEMM_SMEM_BYTES);
    cudaFuncSetAttribute(gemm_out_kernel, cudaFuncAttributeMaxDynamicSharedMemorySize,
                         GEMM_SMEM_BYTES);
    cudaFuncSetAttribute(attn_kernel, cudaFuncAttributeMaxDynamicSharedMemorySize,
                         ATT_SMEM_BYTES);

    const int CVT_BLOCKS = (MROWS*DMODEL/4 + 4*DMODEL*DMODEL/4) / 256;  // 24576
    cvt_all_kernel<<<CVT_BLOCKS, 256>>>(x, wq, wk, wv, wo);
    gemm_qkv_kernel<<<dim3(DMODEL/GBN, MROWS/GBM, 3), 256, GEMM_SMEM_BYTES>>>(bq, bk, bv);
    attn_kernel<<<dim3(SEQ/128, BATCH*NH), 512, ATT_SMEM_BYTES>>>();
    gemm_out_kernel<<<dim3(DMODEL/GBN, MROWS/GBM), 256, GEMM_SMEM_BYTES>>>(bo, out);
}